// round 1
// baseline (speedup 1.0000x reference)
#include <cuda_runtime.h>

#define WL_L     2048
#define WL_LMASK 2047
#define WL_D     32
#define WL_B     16
#define WL_NT    256
#define WL_ITERS (WL_L / WL_NT)   // 8

__global__ __launch_bounds__(WL_NT) void wavelet_db4_kernel(
    const float* __restrict__ x,       // (B, L, D)
    const float* __restrict__ w_dec,   // (4, L, L) — only 8 taps read
    const float* __restrict__ v_dec,   // (4, L, L) — only 8 taps read
    float* __restrict__ out)           // (B, D, L, 5)
{
    __shared__ float xs[WL_L];
    __shared__ float v0s[WL_L];
    __shared__ float v1s[WL_L];
    __shared__ float v2s[WL_L];
    __shared__ float gs[8];
    __shared__ float hs[8];

    const int tid = threadIdx.x;
    const int bd  = blockIdx.x;         // bd = b*32 + d
    const int b   = bd >> 5;
    const int d   = bd & 31;

    // Recover the 8 taps from row 0 of level-0 filters:
    //   filter[0][0][(0 - i) mod L] = tap[i]  ->  col 0 for i=0, col L-i for i>=1
    if (tid < 8) {
        int col = (WL_L - tid) & WL_LMASK;
        gs[tid] = v_dec[col];
        hs[tid] = w_dec[col];
    }

    // Load x[b, :, d] (stride-D column; served from L2 after first touch)
    const float* xp = x + ((size_t)b * WL_L * WL_D) + d;
    #pragma unroll
    for (int k = 0; k < WL_ITERS; k++) {
        int l = tid + k * WL_NT;
        xs[l] = xp[(size_t)l * WL_D];
    }
    __syncthreads();

    float g[8], h[8];
    #pragma unroll
    for (int i = 0; i < 8; i++) { g[i] = gs[i]; h[i] = hs[i]; }

    // v0: dilation 1 on xs
    #pragma unroll
    for (int k = 0; k < WL_ITERS; k++) {
        int m = tid + k * WL_NT;
        float s = 0.f;
        #pragma unroll
        for (int i = 0; i < 8; i++) s += g[i] * xs[(m - i) & WL_LMASK];
        v0s[m] = s;
    }
    __syncthreads();

    // v1: dilation 2 on v0
    #pragma unroll
    for (int k = 0; k < WL_ITERS; k++) {
        int m = tid + k * WL_NT;
        float s = 0.f;
        #pragma unroll
        for (int i = 0; i < 8; i++) s += g[i] * v0s[(m - 2 * i) & WL_LMASK];
        v1s[m] = s;
    }
    __syncthreads();

    // v2: dilation 4 on v1
    #pragma unroll
    for (int k = 0; k < WL_ITERS; k++) {
        int m = tid + k * WL_NT;
        float s = 0.f;
        #pragma unroll
        for (int i = 0; i < 8; i++) s += g[i] * v1s[(m - 4 * i) & WL_LMASK];
        v2s[m] = s;
    }
    __syncthreads();

    // Final: w0 (h⊛xs,1), w1 (h⊛v0,2), w2 (h⊛v1,4), w3 (h⊛v2,8), v3 (g⊛v2,8)
    float* op = out + (size_t)bd * WL_L * 5;
    #pragma unroll
    for (int k = 0; k < WL_ITERS; k++) {
        int m = tid + k * WL_NT;
        float w0 = 0.f, w1 = 0.f, w2 = 0.f, w3 = 0.f, v3 = 0.f;
        #pragma unroll
        for (int i = 0; i < 8; i++) {
            w0 += h[i] * xs [(m -     i) & WL_LMASK];
            w1 += h[i] * v0s[(m - 2 * i) & WL_LMASK];
            w2 += h[i] * v1s[(m - 4 * i) & WL_LMASK];
            float v2v = v2s[(m - 8 * i) & WL_LMASK];
            w3 += h[i] * v2v;
            v3 += g[i] * v2v;
        }
        float* o = op + (size_t)m * 5;
        o[0] = w0; o[1] = w1; o[2] = w2; o[3] = w3; o[4] = v3;
    }
}

extern "C" void kernel_launch(void* const* d_in, const int* in_sizes, int n_in,
                              void* d_out, int out_size) {
    const float* x     = (const float*)d_in[0];
    const float* w_dec = (const float*)d_in[1];
    const float* v_dec = (const float*)d_in[2];
    float* out = (float*)d_out;

    wavelet_db4_kernel<<<WL_B * WL_D, WL_NT>>>(x, w_dec, v_dec, out);
}

// round 2
// speedup vs baseline: 1.2947x; 1.2947x over previous
#include <cuda_runtime.h>

#define WL_L     2048
#define WL_LMASK 2047
#define WL_D     32
#define WL_B     16
#define WL_NT    256

#define WL_T     512                 // outputs per CTA
#define WL_HALO  112                 // >= 105 back-reach of receptive field
#define WL_EXT   (WL_T + WL_HALO)    // 624 staged elements
#define WL_NCHUNK (WL_L / WL_T)      // 4

__global__ __launch_bounds__(WL_NT) void wavelet_db4_kernel(
    const float* __restrict__ x,       // (B, L, D)
    const float* __restrict__ w_dec,   // (4, L, L) — only 8 taps read
    const float* __restrict__ v_dec,   // (4, L, L) — only 8 taps read
    float* __restrict__ out)           // (B, D, L, 5)
{
    __shared__ float xs [WL_EXT];
    __shared__ float v0s[WL_EXT];
    __shared__ float v1s[WL_EXT];
    __shared__ float v2s[WL_EXT];
    __shared__ float gs[8];
    __shared__ float hs[8];

    const int tid   = threadIdx.x;
    const int bd    = blockIdx.x >> 2;           // (b*32 + d)
    const int chunk = blockIdx.x & (WL_NCHUNK - 1);
    const int b     = bd >> 5;
    const int d     = bd & 31;
    const int M0    = chunk * WL_T;               // first output index
    const int base  = M0 - WL_HALO;               // circular base in L

    // Recover the 8 taps from row 0 of level-0 filters:
    //   filter[0][0][(0 - i) mod L] = tap[i]
    if (tid < 8) {
        int col = (WL_L - tid) & WL_LMASK;
        gs[tid] = v_dec[col];
        hs[tid] = w_dec[col];
    }

    // Stage x[b, (base+l) mod L, d] into xs[l] (only place wraparound happens)
    const float* xp = x + ((size_t)b * WL_L * WL_D) + d;
    #pragma unroll
    for (int l = tid; l < WL_EXT; l += WL_NT) {
        int gl = (base + l) & WL_LMASK;
        xs[l] = xp[(size_t)gl * WL_D];
    }
    __syncthreads();

    float g[8], h[8];
    #pragma unroll
    for (int i = 0; i < 8; i++) { g[i] = gs[i]; h[i] = hs[i]; }

    // v0: dilation 1 (valid for l >= 7)
    #pragma unroll
    for (int l = tid; l < WL_EXT; l += WL_NT) {
        if (l >= 7) {
            float s = 0.f;
            #pragma unroll
            for (int i = 0; i < 8; i++) s += g[i] * xs[l - i];
            v0s[l] = s;
        }
    }
    __syncthreads();

    // v1: dilation 2 (valid for l >= 21)
    #pragma unroll
    for (int l = tid; l < WL_EXT; l += WL_NT) {
        if (l >= 21) {
            float s = 0.f;
            #pragma unroll
            for (int i = 0; i < 8; i++) s += g[i] * v0s[l - 2 * i];
            v1s[l] = s;
        }
    }
    __syncthreads();

    // v2: dilation 4 (valid for l >= 49)
    #pragma unroll
    for (int l = tid; l < WL_EXT; l += WL_NT) {
        if (l >= 49) {
            float s = 0.f;
            #pragma unroll
            for (int i = 0; i < 8; i++) s += g[i] * v1s[l - 4 * i];
            v2s[l] = s;
        }
    }
    __syncthreads();

    // Final: w0 (h⊛x,1), w1 (h⊛v0,2), w2 (h⊛v1,4), w3 (h⊛v2,8), v3 (g⊛v2,8)
    float* op = out + (size_t)bd * WL_L * 5;
    #pragma unroll
    for (int l = tid + WL_HALO; l < WL_EXT; l += WL_NT) {
        float w0 = 0.f, w1 = 0.f, w2 = 0.f, w3 = 0.f, v3 = 0.f;
        #pragma unroll
        for (int i = 0; i < 8; i++) {
            w0 += h[i] * xs [l -     i];
            w1 += h[i] * v0s[l - 2 * i];
            w2 += h[i] * v1s[l - 4 * i];
            float v2v = v2s[l - 8 * i];
            w3 += h[i] * v2v;
            v3 += g[i] * v2v;
        }
        int m = M0 + (l - WL_HALO);
        float* o = op + (size_t)m * 5;
        o[0] = w0; o[1] = w1; o[2] = w2; o[3] = w3; o[4] = v3;
    }
}

extern "C" void kernel_launch(void* const* d_in, const int* in_sizes, int n_in,
                              void* d_out, int out_size) {
    const float* x     = (const float*)d_in[0];
    const float* w_dec = (const float*)d_in[1];
    const float* v_dec = (const float*)d_in[2];
    float* out = (float*)d_out;

    wavelet_db4_kernel<<<WL_B * WL_D * WL_NCHUNK, WL_NT>>>(x, w_dec, v_dec, out);
}

// round 3
// speedup vs baseline: 1.4157x; 1.0935x over previous
#include <cuda_runtime.h>

#define WL_L      2048
#define WL_LMASK  2047
#define WL_D      32
#define WL_B      16
#define WL_NT     256
#define WL_T      1024                // outputs per CTA
#define WL_HALO   128                 // >= 105 back-reach, multiple of 4
#define WL_EXT    (WL_T + WL_HALO)    // 1152
#define WL_NCHUNK (WL_L / WL_T)       // 2

__global__ __launch_bounds__(WL_NT) void wavelet_db4_kernel(
    const float* __restrict__ x,       // (B, L, D)
    const float* __restrict__ w_dec,   // (4, L, L) — only 8 taps read
    const float* __restrict__ v_dec,   // (4, L, L) — only 8 taps read
    float* __restrict__ out)           // (B, D, L, 5)
{
    __shared__ float xs [WL_EXT];
    __shared__ float v0s[WL_EXT];
    __shared__ float v1s[WL_EXT];
    __shared__ float v2s[WL_EXT];
    __shared__ float gs[8];
    __shared__ float hs[8];

    const int tid   = threadIdx.x;
    const int bd    = blockIdx.x >> 1;            // b*32 + d
    const int chunk = blockIdx.x & (WL_NCHUNK - 1);
    const int b     = bd >> 5;
    const int d     = bd & 31;
    const int M0    = chunk * WL_T;
    const int base  = M0 - WL_HALO;

    // taps live in row 0 of level-0 filters: f[0][0][(0-i) mod L] = tap[i]
    if (tid < 8) {
        int col = (WL_L - tid) & WL_LMASK;
        gs[tid] = v_dec[col];
        hs[tid] = w_dec[col];
    }

    // stage x[b, (base+l) mod L, d]
    const float* xp = x + ((size_t)b * WL_L * WL_D) + d;
    #pragma unroll
    for (int l = tid; l < WL_EXT; l += WL_NT) {
        int gl = (base + l) & WL_LMASK;
        xs[l] = xp[(size_t)gl * WL_D];
    }
    __syncthreads();

    float g[8], h[8];
    #pragma unroll
    for (int i = 0; i < 8; i++) { g[i] = gs[i]; h[i] = hs[i]; }

    const float4* xs4  = (const float4*)xs;
    const float4* v0s4 = (const float4*)v0s;
    const float4* v1s4 = (const float4*)v1s;
    const float4* v2s4 = (const float4*)v2s;

    // ── v0: dilation 1. window xs[l0-8 .. l0+3] (12 floats, 3 LDS.128)
    #pragma unroll
    for (int l0 = tid * 4; l0 < WL_EXT; l0 += WL_NT * 4) {
        if (l0 >= 8) {
            int wb = (l0 - 8) >> 2;
            float4 a = xs4[wb], bb = xs4[wb + 1], c = xs4[wb + 2];
            float win[12] = {a.x,a.y,a.z,a.w, bb.x,bb.y,bb.z,bb.w, c.x,c.y,c.z,c.w};
            float a0=0.f, a1=0.f, a2=0.f, a3=0.f;
            #pragma unroll
            for (int i = 0; i < 8; i++) {
                a0 += g[i] * win[ 8 - i];
                a1 += g[i] * win[ 9 - i];
                a2 += g[i] * win[10 - i];
                a3 += g[i] * win[11 - i];
            }
            ((float4*)v0s)[l0 >> 2] = make_float4(a0, a1, a2, a3);
        }
    }
    __syncthreads();

    // ── v1: dilation 2. window v0s[l0-16 .. l0+3] (20 floats, 5 LDS.128)
    #pragma unroll
    for (int l0 = tid * 4; l0 < WL_EXT; l0 += WL_NT * 4) {
        if (l0 >= 16) {
            int wb = (l0 - 16) >> 2;
            float win[20];
            #pragma unroll
            for (int k = 0; k < 5; k++) {
                float4 q = v0s4[wb + k];
                win[4*k] = q.x; win[4*k+1] = q.y; win[4*k+2] = q.z; win[4*k+3] = q.w;
            }
            float a0=0.f, a1=0.f, a2=0.f, a3=0.f;
            #pragma unroll
            for (int i = 0; i < 8; i++) {
                a0 += g[i] * win[16 - 2*i];
                a1 += g[i] * win[17 - 2*i];
                a2 += g[i] * win[18 - 2*i];
                a3 += g[i] * win[19 - 2*i];
            }
            ((float4*)v1s)[l0 >> 2] = make_float4(a0, a1, a2, a3);
        }
    }
    __syncthreads();

    // ── v2: dilation 4. one aligned float4 per tap: v1s4[l0/4 - i]
    #pragma unroll
    for (int l0 = tid * 4; l0 < WL_EXT; l0 += WL_NT * 4) {
        if (l0 >= 28) {
            int b4 = l0 >> 2;
            float a0=0.f, a1=0.f, a2=0.f, a3=0.f;
            #pragma unroll
            for (int i = 0; i < 8; i++) {
                float4 q = v1s4[b4 - i];
                a0 += g[i] * q.x; a1 += g[i] * q.y;
                a2 += g[i] * q.z; a3 += g[i] * q.w;
            }
            ((float4*)v2s)[l0 >> 2] = make_float4(a0, a1, a2, a3);
        }
    }
    __syncthreads();

    // ── final: each thread produces 4 outputs at l0 = HALO + 4*tid
    {
        const int l0 = WL_HALO + 4 * tid;
        const int b4 = l0 >> 2;
        float w0[4] = {0,0,0,0}, w1[4] = {0,0,0,0}, w2[4] = {0,0,0,0};
        float w3[4] = {0,0,0,0}, v3[4] = {0,0,0,0};

        // w0: h ⊛ x, dilation 1 (window, 3 LDS.128)
        {
            int wb = (l0 - 8) >> 2;
            float4 a = xs4[wb], bb = xs4[wb + 1], c = xs4[wb + 2];
            float win[12] = {a.x,a.y,a.z,a.w, bb.x,bb.y,bb.z,bb.w, c.x,c.y,c.z,c.w};
            #pragma unroll
            for (int i = 0; i < 8; i++) {
                w0[0] += h[i] * win[ 8 - i];
                w0[1] += h[i] * win[ 9 - i];
                w0[2] += h[i] * win[10 - i];
                w0[3] += h[i] * win[11 - i];
            }
        }
        // w1: h ⊛ v0, dilation 2 (window, 5 LDS.128)
        {
            int wb = (l0 - 16) >> 2;
            float win[20];
            #pragma unroll
            for (int k = 0; k < 5; k++) {
                float4 q = v0s4[wb + k];
                win[4*k] = q.x; win[4*k+1] = q.y; win[4*k+2] = q.z; win[4*k+3] = q.w;
            }
            #pragma unroll
            for (int i = 0; i < 8; i++) {
                w1[0] += h[i] * win[16 - 2*i];
                w1[1] += h[i] * win[17 - 2*i];
                w1[2] += h[i] * win[18 - 2*i];
                w1[3] += h[i] * win[19 - 2*i];
            }
        }
        // w2: h ⊛ v1, dilation 4 (one float4 per tap)
        #pragma unroll
        for (int i = 0; i < 8; i++) {
            float4 q = v1s4[b4 - i];
            w2[0] += h[i] * q.x; w2[1] += h[i] * q.y;
            w2[2] += h[i] * q.z; w2[3] += h[i] * q.w;
        }
        // w3, v3: dilation 8 on v2 (one float4 per tap, shared read)
        #pragma unroll
        for (int i = 0; i < 8; i++) {
            float4 q = v2s4[b4 - 2*i];
            w3[0] += h[i] * q.x; w3[1] += h[i] * q.y;
            w3[2] += h[i] * q.z; w3[3] += h[i] * q.w;
            v3[0] += g[i] * q.x; v3[1] += g[i] * q.y;
            v3[2] += g[i] * q.z; v3[3] += g[i] * q.w;
        }

        // pack 4 outputs × 5 coeffs = 20 contiguous floats → 5 STG.128
        float o[20];
        #pragma unroll
        for (int j = 0; j < 4; j++) {
            o[j*5 + 0] = w0[j];
            o[j*5 + 1] = w1[j];
            o[j*5 + 2] = w2[j];
            o[j*5 + 3] = w3[j];
            o[j*5 + 4] = v3[j];
        }
        const int m0 = M0 + 4 * tid;
        float4* og = (float4*)(out + ((size_t)bd * WL_L + m0) * 5);
        #pragma unroll
        for (int k = 0; k < 5; k++) og[k] = ((const float4*)o)[k];
    }
}

extern "C" void kernel_launch(void* const* d_in, const int* in_sizes, int n_in,
                              void* d_out, int out_size) {
    const float* x     = (const float*)d_in[0];
    const float* w_dec = (const float*)d_in[1];
    const float* v_dec = (const float*)d_in[2];
    float* out = (float*)d_out;

    wavelet_db4_kernel<<<WL_B * WL_D * WL_NCHUNK, WL_NT>>>(x, w_dec, v_dec, out);
}

// round 4
// speedup vs baseline: 1.6091x; 1.1366x over previous
#include <cuda_runtime.h>

#define WL_L      2048
#define WL_LMASK  2047
#define WL_D      32
#define WL_B      16
#define WL_NT     256

#define WL_G      4                   // d-planes per CTA
#define WL_T      256                 // outputs per plane per CTA
#define WL_HALO   112                 // >= 105 back-reach, multiple of 4
#define WL_EXT    (WL_T + WL_HALO)    // 368
#define WL_NCHUNK (WL_L / WL_T)       // 8
#define WL_NDG    (WL_D / WL_G)       // 8
#define WL_PT     (WL_NT / WL_G)      // 64 threads per plane

__global__ __launch_bounds__(WL_NT) void wavelet_db4_kernel(
    const float* __restrict__ x,       // (B, L, D)
    const float* __restrict__ w_dec,   // (4, L, L) — only 8 taps read
    const float* __restrict__ v_dec,   // (4, L, L) — only 8 taps read
    float* __restrict__ out)           // (B, D, L, 5)
{
    __shared__ float xs [WL_G][WL_EXT];
    __shared__ float v0s[WL_G][WL_EXT];
    __shared__ float v1s[WL_G][WL_EXT];
    __shared__ float v2s[WL_G][WL_EXT];
    __shared__ float gs[8];
    __shared__ float hs[8];

    const int tid   = threadIdx.x;
    const int blk   = blockIdx.x;
    const int chunk = blk & (WL_NCHUNK - 1);
    const int dg    = (blk >> 3) & (WL_NDG - 1);
    const int b     = blk >> 6;
    const int M0    = chunk * WL_T;
    const int base  = M0 - WL_HALO;

    const int p = tid >> 6;           // plane 0..3
    const int q = tid & (WL_PT - 1);  // slot in plane 0..63

    // taps from row 0 of level-0 filters: f[0][0][(0-i) mod L] = tap[i]
    if (tid < 8) {
        int col = (WL_L - tid) & WL_LMASK;
        gs[tid] = v_dec[col];
        hs[tid] = w_dec[col];
    }

    // Coalesced-amortized gather: one float4 across 4 adjacent d per row.
    {
        const float* xp = x + ((size_t)b * WL_L * WL_D) + dg * WL_G;
        for (int l = tid; l < WL_EXT; l += WL_NT) {
            int gl = (base + l) & WL_LMASK;
            float4 qv = *(const float4*)(xp + (size_t)gl * WL_D);
            xs[0][l] = qv.x; xs[1][l] = qv.y; xs[2][l] = qv.z; xs[3][l] = qv.w;
        }
    }
    __syncthreads();

    float g[8], h[8];
    #pragma unroll
    for (int i = 0; i < 8; i++) { g[i] = gs[i]; h[i] = hs[i]; }

    const float4* xs4  = (const float4*)(&xs [p][0]);
    const float4* v0s4 = (const float4*)(&v0s[p][0]);
    const float4* v1s4 = (const float4*)(&v1s[p][0]);
    const float4* v2s4 = (const float4*)(&v2s[p][0]);

    // ── v0: dilation 1. window xs[l0-8 .. l0+3] (3 LDS.128)
    #pragma unroll
    for (int k = 0; k < 2; k++) {
        int l0 = 4 * (q + WL_PT * k);
        if (l0 >= 8 && l0 < WL_EXT) {
            int wb = (l0 - 8) >> 2;
            float4 a = xs4[wb], bb = xs4[wb + 1], c = xs4[wb + 2];
            float win[12] = {a.x,a.y,a.z,a.w, bb.x,bb.y,bb.z,bb.w, c.x,c.y,c.z,c.w};
            float a0=0.f, a1=0.f, a2=0.f, a3=0.f;
            #pragma unroll
            for (int i = 0; i < 8; i++) {
                a0 += g[i] * win[ 8 - i];
                a1 += g[i] * win[ 9 - i];
                a2 += g[i] * win[10 - i];
                a3 += g[i] * win[11 - i];
            }
            ((float4*)(&v0s[p][0]))[l0 >> 2] = make_float4(a0, a1, a2, a3);
        }
    }
    __syncthreads();

    // ── v1: dilation 2. window v0s[l0-16 .. l0+3] (5 LDS.128)
    #pragma unroll
    for (int k = 0; k < 2; k++) {
        int l0 = 4 * (q + WL_PT * k);
        if (l0 >= 16 && l0 < WL_EXT) {
            int wb = (l0 - 16) >> 2;
            float win[20];
            #pragma unroll
            for (int kk = 0; kk < 5; kk++) {
                float4 qv = v0s4[wb + kk];
                win[4*kk] = qv.x; win[4*kk+1] = qv.y; win[4*kk+2] = qv.z; win[4*kk+3] = qv.w;
            }
            float a0=0.f, a1=0.f, a2=0.f, a3=0.f;
            #pragma unroll
            for (int i = 0; i < 8; i++) {
                a0 += g[i] * win[16 - 2*i];
                a1 += g[i] * win[17 - 2*i];
                a2 += g[i] * win[18 - 2*i];
                a3 += g[i] * win[19 - 2*i];
            }
            ((float4*)(&v1s[p][0]))[l0 >> 2] = make_float4(a0, a1, a2, a3);
        }
    }
    __syncthreads();

    // ── v2: dilation 4. one aligned float4 per tap
    #pragma unroll
    for (int k = 0; k < 2; k++) {
        int l0 = 4 * (q + WL_PT * k);
        if (l0 >= 28 && l0 < WL_EXT) {
            int b4 = l0 >> 2;
            float a0=0.f, a1=0.f, a2=0.f, a3=0.f;
            #pragma unroll
            for (int i = 0; i < 8; i++) {
                float4 qv = v1s4[b4 - i];
                a0 += g[i] * qv.x; a1 += g[i] * qv.y;
                a2 += g[i] * qv.z; a3 += g[i] * qv.w;
            }
            ((float4*)(&v2s[p][0]))[l0 >> 2] = make_float4(a0, a1, a2, a3);
        }
    }
    __syncthreads();

    // ── final: one quad of outputs per thread at l0 = HALO + 4q
    {
        const int l0 = WL_HALO + 4 * q;
        const int b4 = l0 >> 2;
        float w0[4] = {0,0,0,0}, w1[4] = {0,0,0,0}, w2[4] = {0,0,0,0};
        float w3[4] = {0,0,0,0}, v3[4] = {0,0,0,0};

        // w0: h ⊛ x, dilation 1
        {
            int wb = (l0 - 8) >> 2;
            float4 a = xs4[wb], bb = xs4[wb + 1], c = xs4[wb + 2];
            float win[12] = {a.x,a.y,a.z,a.w, bb.x,bb.y,bb.z,bb.w, c.x,c.y,c.z,c.w};
            #pragma unroll
            for (int i = 0; i < 8; i++) {
                w0[0] += h[i] * win[ 8 - i];
                w0[1] += h[i] * win[ 9 - i];
                w0[2] += h[i] * win[10 - i];
                w0[3] += h[i] * win[11 - i];
            }
        }
        // w1: h ⊛ v0, dilation 2
        {
            int wb = (l0 - 16) >> 2;
            float win[20];
            #pragma unroll
            for (int kk = 0; kk < 5; kk++) {
                float4 qv = v0s4[wb + kk];
                win[4*kk] = qv.x; win[4*kk+1] = qv.y; win[4*kk+2] = qv.z; win[4*kk+3] = qv.w;
            }
            #pragma unroll
            for (int i = 0; i < 8; i++) {
                w1[0] += h[i] * win[16 - 2*i];
                w1[1] += h[i] * win[17 - 2*i];
                w1[2] += h[i] * win[18 - 2*i];
                w1[3] += h[i] * win[19 - 2*i];
            }
        }
        // w2: h ⊛ v1, dilation 4
        #pragma unroll
        for (int i = 0; i < 8; i++) {
            float4 qv = v1s4[b4 - i];
            w2[0] += h[i] * qv.x; w2[1] += h[i] * qv.y;
            w2[2] += h[i] * qv.z; w2[3] += h[i] * qv.w;
        }
        // w3, v3: dilation 8 on v2 (shared reads)
        #pragma unroll
        for (int i = 0; i < 8; i++) {
            float4 qv = v2s4[b4 - 2*i];
            w3[0] += h[i] * qv.x; w3[1] += h[i] * qv.y;
            w3[2] += h[i] * qv.z; w3[3] += h[i] * qv.w;
            v3[0] += g[i] * qv.x; v3[1] += g[i] * qv.y;
            v3[2] += g[i] * qv.z; v3[3] += g[i] * qv.w;
        }

        float o[20];
        #pragma unroll
        for (int j = 0; j < 4; j++) {
            o[j*5 + 0] = w0[j];
            o[j*5 + 1] = w1[j];
            o[j*5 + 2] = w2[j];
            o[j*5 + 3] = w3[j];
            o[j*5 + 4] = v3[j];
        }
        const int bd = b * WL_D + dg * WL_G + p;
        const int m0 = M0 + 4 * q;
        float4* og = (float4*)(out + ((size_t)bd * WL_L + m0) * 5);
        #pragma unroll
        for (int kk = 0; kk < 5; kk++) og[kk] = ((const float4*)o)[kk];
    }
}

extern "C" void kernel_launch(void* const* d_in, const int* in_sizes, int n_in,
                              void* d_out, int out_size) {
    const float* x     = (const float*)d_in[0];
    const float* w_dec = (const float*)d_in[1];
    const float* v_dec = (const float*)d_in[2];
    float* out = (float*)d_out;

    wavelet_db4_kernel<<<WL_B * WL_NDG * WL_NCHUNK, WL_NT>>>(x, w_dec, v_dec, out);
}

// round 5
// speedup vs baseline: 1.8237x; 1.1333x over previous
#include <cuda_runtime.h>

#define WL_L      2048
#define WL_LMASK  2047
#define WL_D      32
#define WL_B      16
#define WL_NT     256

#define WL_G      4                   // d-planes per CTA
#define WL_T      256                 // outputs per plane per CTA
#define WL_HALO   112                 // >= 105 back-reach, multiple of 4
#define WL_EXT    (WL_T + WL_HALO)    // 368
#define WL_NCHUNK (WL_L / WL_T)       // 8
#define WL_NDG    (WL_D / WL_G)       // 8
#define WL_PT     (WL_NT / WL_G)      // 64 threads per plane

__global__ __launch_bounds__(WL_NT) void wavelet_db4_kernel(
    const float* __restrict__ x,       // (B, L, D)
    const float* __restrict__ w_dec,   // (4, L, L) — only 8 taps read
    const float* __restrict__ v_dec,   // (4, L, L) — only 8 taps read
    float* __restrict__ out)           // (B, D, L, 5)
{
    __shared__ float xs [WL_G][WL_EXT];
    __shared__ float v0s[WL_G][WL_EXT];
    __shared__ float v1s[WL_G][WL_EXT];
    __shared__ float v2s[WL_G][WL_EXT];
    __shared__ float gs[8];
    __shared__ float hs[8];

    const int tid   = threadIdx.x;
    const int blk   = blockIdx.x;
    const int chunk = blk & (WL_NCHUNK - 1);
    const int dg    = (blk >> 3) & (WL_NDG - 1);
    const int b     = blk >> 6;
    const int M0    = chunk * WL_T;
    const int base  = M0 - WL_HALO;

    const int p = tid >> 6;           // plane 0..3
    const int q = tid & (WL_PT - 1);  // slot in plane 0..63

    // halo side-job: 28 halo quads split 14/14 across the plane's two warps
    int hq = -1;
    if (q >= 18 && q < 32)      hq = q - 18;   // 0..13  (warp A lanes 18-31)
    else if (q >= 50)           hq = q - 36;   // 14..27 (warp B lanes 18-31)

    // taps from row 0 of level-0 filters: f[0][0][(0-i) mod L] = tap[i]
    if (tid < 8) {
        int col = (WL_L - tid) & WL_LMASK;
        gs[tid] = v_dec[col];
        hs[tid] = w_dec[col];
    }

    // amortized gather: one float4 across 4 adjacent d per x-row
    {
        const float* xp = x + ((size_t)b * WL_L * WL_D) + dg * WL_G;
        for (int l = tid; l < WL_EXT; l += WL_NT) {
            int gl = (base + l) & WL_LMASK;
            float4 qv = *(const float4*)(xp + (size_t)gl * WL_D);
            xs[0][l] = qv.x; xs[1][l] = qv.y; xs[2][l] = qv.z; xs[3][l] = qv.w;
        }
    }
    __syncthreads();

    float g[8], h[8];
    #pragma unroll
    for (int i = 0; i < 8; i++) { g[i] = gs[i]; h[i] = hs[i]; }

    const float4* xs4  = (const float4*)(&xs [p][0]);
    const float4* v0s4 = (const float4*)(&v0s[p][0]);
    const float4* v1s4 = (const float4*)(&v1s[p][0]);
    const float4* v2s4 = (const float4*)(&v2s[p][0]);
    float4* v0s4w = (float4*)(&v0s[p][0]);
    float4* v1s4w = (float4*)(&v1s[p][0]);
    float4* v2s4w = (float4*)(&v2s[p][0]);

    const int l0 = WL_HALO + 4 * q;   // this thread's output quad
    const int b4 = l0 >> 2;           // 28 + q

    float w0[4], w1[4], w2[4];

    // ── stage 1: dilation 1 on xs → v0 (g) + w0 (h), window loaded once
    {
        int wb = b4 - 2;              // (l0-8)>>2
        float4 a = xs4[wb], bb = xs4[wb + 1], c = xs4[wb + 2];
        float win[12] = {a.x,a.y,a.z,a.w, bb.x,bb.y,bb.z,bb.w, c.x,c.y,c.z,c.w};
        float vg[4] = {0,0,0,0}; float vh[4] = {0,0,0,0};
        #pragma unroll
        for (int i = 0; i < 8; i++) {
            #pragma unroll
            for (int j = 0; j < 4; j++) {
                vg[j] += g[i] * win[8 + j - i];
                vh[j] += h[i] * win[8 + j - i];
            }
        }
        v0s4w[b4] = make_float4(vg[0], vg[1], vg[2], vg[3]);
        #pragma unroll
        for (int j = 0; j < 4; j++) w0[j] = vh[j];

        if (hq >= 2) {                // halo v0 (g only), valid l0h >= 8
            int hl0 = 4 * hq, wbh = (hl0 - 8) >> 2;
            float4 ha = xs4[wbh], hb = xs4[wbh + 1], hc = xs4[wbh + 2];
            float hw[12] = {ha.x,ha.y,ha.z,ha.w, hb.x,hb.y,hb.z,hb.w, hc.x,hc.y,hc.z,hc.w};
            float a0=0.f, a1=0.f, a2=0.f, a3=0.f;
            #pragma unroll
            for (int i = 0; i < 8; i++) {
                a0 += g[i] * hw[ 8 - i]; a1 += g[i] * hw[ 9 - i];
                a2 += g[i] * hw[10 - i]; a3 += g[i] * hw[11 - i];
            }
            v0s4w[hq] = make_float4(a0, a1, a2, a3);
        }
    }
    __syncthreads();

    // ── stage 2: dilation 2 on v0 → v1 (g) + w1 (h)
    {
        int wb = b4 - 4;              // (l0-16)>>2
        float win[20];
        #pragma unroll
        for (int kk = 0; kk < 5; kk++) {
            float4 qv = v0s4[wb + kk];
            win[4*kk] = qv.x; win[4*kk+1] = qv.y; win[4*kk+2] = qv.z; win[4*kk+3] = qv.w;
        }
        float vg[4] = {0,0,0,0}; float vh[4] = {0,0,0,0};
        #pragma unroll
        for (int i = 0; i < 8; i++) {
            #pragma unroll
            for (int j = 0; j < 4; j++) {
                vg[j] += g[i] * win[16 + j - 2*i];
                vh[j] += h[i] * win[16 + j - 2*i];
            }
        }
        v1s4w[b4] = make_float4(vg[0], vg[1], vg[2], vg[3]);
        #pragma unroll
        for (int j = 0; j < 4; j++) w1[j] = vh[j];

        if (hq >= 7) {                // halo v1 (g only), valid l0h >= 28
            int hl0 = 4 * hq, wbh = (hl0 - 16) >> 2;
            float hw[20];
            #pragma unroll
            for (int kk = 0; kk < 5; kk++) {
                float4 qv = v0s4[wbh + kk];
                hw[4*kk] = qv.x; hw[4*kk+1] = qv.y; hw[4*kk+2] = qv.z; hw[4*kk+3] = qv.w;
            }
            float a0=0.f, a1=0.f, a2=0.f, a3=0.f;
            #pragma unroll
            for (int i = 0; i < 8; i++) {
                a0 += g[i] * hw[16 - 2*i]; a1 += g[i] * hw[17 - 2*i];
                a2 += g[i] * hw[18 - 2*i]; a3 += g[i] * hw[19 - 2*i];
            }
            v1s4w[hq] = make_float4(a0, a1, a2, a3);
        }
    }
    __syncthreads();

    // ── stage 3: dilation 4 on v1 → v2 (g) + w2 (h); one float4 per tap
    {
        float vg[4] = {0,0,0,0}; float vh[4] = {0,0,0,0};
        #pragma unroll
        for (int i = 0; i < 8; i++) {
            float4 qv = v1s4[b4 - i];
            vg[0] += g[i] * qv.x; vg[1] += g[i] * qv.y;
            vg[2] += g[i] * qv.z; vg[3] += g[i] * qv.w;
            vh[0] += h[i] * qv.x; vh[1] += h[i] * qv.y;
            vh[2] += h[i] * qv.z; vh[3] += h[i] * qv.w;
        }
        v2s4w[b4] = make_float4(vg[0], vg[1], vg[2], vg[3]);
        #pragma unroll
        for (int j = 0; j < 4; j++) w2[j] = vh[j];

        if (hq >= 14) {               // halo v2 (g only), valid l0h >= 56
            int hb4 = hq;
            float a0=0.f, a1=0.f, a2=0.f, a3=0.f;
            #pragma unroll
            for (int i = 0; i < 8; i++) {
                float4 qv = v1s4[hb4 - i];
                a0 += g[i] * qv.x; a1 += g[i] * qv.y;
                a2 += g[i] * qv.z; a3 += g[i] * qv.w;
            }
            v2s4w[hq] = make_float4(a0, a1, a2, a3);
        }
    }
    __syncthreads();

    // ── stage 4: dilation 8 on v2 → w3 (h) + v3 (g); write all 5 coeffs
    {
        float w3[4] = {0,0,0,0}, v3[4] = {0,0,0,0};
        #pragma unroll
        for (int i = 0; i < 8; i++) {
            float4 qv = v2s4[b4 - 2*i];
            w3[0] += h[i] * qv.x; w3[1] += h[i] * qv.y;
            w3[2] += h[i] * qv.z; w3[3] += h[i] * qv.w;
            v3[0] += g[i] * qv.x; v3[1] += g[i] * qv.y;
            v3[2] += g[i] * qv.z; v3[3] += g[i] * qv.w;
        }

        float o[20];
        #pragma unroll
        for (int j = 0; j < 4; j++) {
            o[j*5 + 0] = w0[j];
            o[j*5 + 1] = w1[j];
            o[j*5 + 2] = w2[j];
            o[j*5 + 3] = w3[j];
            o[j*5 + 4] = v3[j];
        }
        const int bd = b * WL_D + dg * WL_G + p;
        const int m0 = M0 + 4 * q;
        float4* og = (float4*)(out + ((size_t)bd * WL_L + m0) * 5);
        #pragma unroll
        for (int kk = 0; kk < 5; kk++) og[kk] = ((const float4*)o)[kk];
    }
}

extern "C" void kernel_launch(void* const* d_in, const int* in_sizes, int n_in,
                              void* d_out, int out_size) {
    const float* x     = (const float*)d_in[0];
    const float* w_dec = (const float*)d_in[1];
    const float* v_dec = (const float*)d_in[2];
    float* out = (float*)d_out;

    wavelet_db4_kernel<<<WL_B * WL_NDG * WL_NCHUNK, WL_NT>>>(x, w_dec, v_dec, out);
}